// round 16
// baseline (speedup 1.0000x reference)
#include <cuda_runtime.h>

#define NHEADS 8
#define HDIM   64
#define TNUM   10
#define QDIM   256
#define NBATCH 131072

#define GPITCH 12            // per-head group pitch (10 used + 2 pad)
#define MPITCH 96            // 8 groups * 12 floats
#define BK     64            // k-tile
#define NKT    (QDIM / BK)   // 4
#define BM     128           // rows per block (4 per thread)
#define TPB    256

#define A_ELEMS  (BK * 128)        // transposed X tile [k][row], 32KB
#define M_ELEMS  (BK * MPITCH)     // 24KB
#define KR_ELEMS (TNUM * HDIM)     // 640
#define SMEM_BYTES ((A_ELEMS + M_ELEMS + KR_ELEMS) * 4)

// Precomputed fused projection matrix in grouped layout:
// M_g[k][h*GPITCH + t],  scores[h,n,t] = sum_k X[n,k] * M[k][h*GPITCH+t]
__device__ float M_g[QDIM * MPITCH];

__global__ void precompute_M(const float* __restrict__ embed,
                             const float* __restrict__ Wq,
                             const float* __restrict__ Wk) {
    const int col = blockIdx.x;          // 0..79
    const int h = col / TNUM;
    const int t = col % TNUM;
    __shared__ float kv[HDIM];
    const int tid = threadIdx.x;         // 0..255
    if (tid < HDIM) {
        const int e = h * HDIM + tid;
        float s = 0.f;
        #pragma unroll
        for (int d = 0; d < HDIM; ++d)
            s += tanhf(embed[t * HDIM + d]) * Wk[e * HDIM + d];
        kv[tid] = s;
    }
    __syncthreads();
    float s = 0.f;
    #pragma unroll
    for (int dd = 0; dd < HDIM; ++dd)
        s += Wq[(h * HDIM + dd) * QDIM + tid] * kv[dd];
    M_g[tid * MPITCH + h * GPITCH + t] = s * 0.125f;
}

// ---- packed f32x2 helpers (FFMA2: 2x fp32 FMA throughput on sm_103a) ----
__device__ __forceinline__ unsigned long long splat2(float x) {
    unsigned long long r;
    asm("mov.b64 %0, {%1, %1};" : "=l"(r) : "r"(__float_as_uint(x)));
    return r;
}
__device__ __forceinline__ void fma2(unsigned long long& d,
                                     unsigned long long a,
                                     unsigned long long b) {
    asm("fma.rn.f32x2 %0, %1, %2, %0;" : "+l"(d) : "l"(a), "l"(b));
}
__device__ __forceinline__ float2 unpack2(unsigned long long v) {
    float lo, hi;
    asm("mov.b64 {%0, %1}, %2;" : "=f"(lo), "=f"(hi) : "l"(v));
    return make_float2(lo, hi);
}

__global__ __launch_bounds__(TPB, 2)
void fused_attn(const float* __restrict__ X,
                const float* __restrict__ embed,
                float* __restrict__ style,   // [N][512]
                float* __restrict__ attn)    // [8][N][10]
{
    extern __shared__ __align__(16) float smem_dyn[];
    float* A_sh  = smem_dyn;                       // [BK][128] xor-swizzled
    float* M_sh  = smem_dyn + A_ELEMS;             // [BK][MPITCH]
    float* kr_sh = smem_dyn + A_ELEMS + M_ELEMS;   // [640]

    const int tid = threadIdx.x;
    const int rg = tid >> 3;     // 0..31 : row-group (4 rows each)
    const int cg = tid & 7;      // 0..7  : head
    const int rowBase = blockIdx.x * BM;

    for (int i = tid; i < KR_ELEMS; i += TPB)
        kr_sh[i] = tanhf(embed[i]);

    unsigned long long acc[4][5];   // 4 rows x 5 col-pairs
    #pragma unroll
    for (int r = 0; r < 4; ++r)
        #pragma unroll
        for (int j = 0; j < 5; ++j)
            acc[r][j] = 0ull;

    // A staging assignment: thread covers one row-half (32 k) per tile
    const int arow = tid >> 1;           // 0..127
    const int ah   = (tid & 1) * 32;     // k-half within tile
    const float* asrc = X + ((size_t)rowBase + arow) * QDIM + ah;

    for (int t = 0; t < NKT; ++t) {
        __syncthreads();
        // stage M tile: 1536 float4, 6 per thread (L2-resident source)
        {
            const float4* src = (const float4*)(M_g + t * M_ELEMS);
            float4* dst = (float4*)M_sh;
            #pragma unroll
            for (int j = 0; j < 6; ++j)
                dst[tid + TPB * j] = src[tid + TPB * j];
        }
        // stage A tile transposed: A_sh[k*128 + (row ^ ((k>>4)<<2))] = X[row][k]
        {
            const float* src = asrc + t * BK;
            #pragma unroll
            for (int j = 0; j < 8; ++j) {
                const float4 v = *(const float4*)(src + j * 4);
                const int k0 = ah + j * 4;            // same (k>>4) group for k0..k0+3
                float* d = A_sh + k0 * 128 + (arow ^ ((k0 >> 4) << 2));
                d[0]   = v.x;
                d[128] = v.y;
                d[256] = v.z;
                d[384] = v.w;
            }
        }
        __syncthreads();

        // compute: per k, 1x LDS.128 (4 rows) + 3 LDS (M) + 20 FMA2
        #pragma unroll
        for (int kq = 0; kq < 4; ++kq) {
            const float* aptr = A_sh + kq * 16 * 128 + ((rg * 4) ^ (kq << 2));
            const float* mptr = M_sh + kq * 16 * MPITCH + cg * GPITCH;
            #pragma unroll 4
            for (int kk = 0; kk < 16; ++kk) {
                const float4 av = *(const float4*)(aptr + kk * 128);
                const float* mrow = mptr + kk * MPITCH;
                const ulonglong2 m01 = *(const ulonglong2*)mrow;
                const ulonglong2 m23 = *(const ulonglong2*)(mrow + 4);
                const unsigned long long m4 = *(const unsigned long long*)(mrow + 8);
                #pragma unroll
                for (int r = 0; r < 4; ++r) {
                    const unsigned long long s = splat2(((const float*)&av)[r]);
                    fma2(acc[r][0], s, m01.x);
                    fma2(acc[r][1], s, m01.y);
                    fma2(acc[r][2], s, m23.x);
                    fma2(acc[r][3], s, m23.y);
                    fma2(acc[r][4], s, m4);
                }
            }
        }
    }

    // ---- epilogue, one row at a time (register-lean) ----
    #pragma unroll
    for (int r = 0; r < 4; ++r) {
        const size_t n = (size_t)rowBase + rg * 4 + r;

        float s10[10];
        #pragma unroll
        for (int j = 0; j < 5; ++j) {
            const float2 f = unpack2(acc[r][j]);
            s10[2 * j]     = f.x;
            s10[2 * j + 1] = f.y;
        }

        // attn_score: [h][n][t], h == cg
        float2* ap = (float2*)(attn + (size_t)cg * NBATCH * TNUM + n * TNUM);
        #pragma unroll
        for (int j = 0; j < 5; ++j)
            ap[j] = make_float2(s10[2 * j], s10[2 * j + 1]);

        // style: out[n, cg*64 + d] = sum_t s10[t] * kr[t][d]
        float* outp = style + n * 512 + cg * 64;
        #pragma unroll
        for (int ch = 0; ch < 4; ++ch) {        // 16-float chunks of d
            unsigned long long o[8] = {0ull,0ull,0ull,0ull,0ull,0ull,0ull,0ull};
            #pragma unroll
            for (int t = 0; t < TNUM; ++t) {
                const unsigned long long sv = splat2(s10[t]);
                const float* kp = kr_sh + t * HDIM + ch * 16;
                const ulonglong2 ka = *(const ulonglong2*)kp;
                const ulonglong2 kb = *(const ulonglong2*)(kp + 4);
                const ulonglong2 kc = *(const ulonglong2*)(kp + 8);
                const ulonglong2 kd = *(const ulonglong2*)(kp + 12);
                fma2(o[0], sv, ka.x);
                fma2(o[1], sv, ka.y);
                fma2(o[2], sv, kb.x);
                fma2(o[3], sv, kb.y);
                fma2(o[4], sv, kc.x);
                fma2(o[5], sv, kc.y);
                fma2(o[6], sv, kd.x);
                fma2(o[7], sv, kd.y);
            }
            #pragma unroll
            for (int q = 0; q < 4; ++q) {
                const float2 f0 = unpack2(o[2 * q]);
                const float2 f1 = unpack2(o[2 * q + 1]);
                *(float4*)(outp + ch * 16 + q * 4) =
                    make_float4(f0.x, f0.y, f1.x, f1.y);
            }
        }
    }
}

extern "C" void kernel_launch(void* const* d_in, const int* in_sizes, int n_in,
                              void* d_out, int out_size) {
    (void)in_sizes; (void)n_in; (void)out_size;
    const float* X     = (const float*)d_in[0];
    const float* embed = (const float*)d_in[1];
    const float* Wq    = (const float*)d_in[2];
    const float* Wk    = (const float*)d_in[3];

    float* style = (float*)d_out;                              // N*512 floats
    float* attn  = (float*)d_out + (size_t)NBATCH * 512;       // 8*N*10 floats

    static int smem_set = 0;
    if (!smem_set) {
        cudaFuncSetAttribute(fused_attn,
                             cudaFuncAttributeMaxDynamicSharedMemorySize,
                             SMEM_BYTES);
        smem_set = 1;
    }

    precompute_M<<<80, 256>>>(embed, Wq, Wk);
    fused_attn<<<NBATCH / BM, TPB, SMEM_BYTES>>>(X, embed, style, attn);
}